// round 13
// baseline (speedup 1.0000x reference)
#include <cuda_runtime.h>
#include <math.h>

#define TB   8
#define TD   512
#define TDD  1024
#define TT   4096
#define NCTA 128
#define CJ   8        // h cols per CTA
#define CI   4        // p cols per CTA
#define NTHR 256
#define NWARP 8
#define NBC  16       // broadcast words (8 CTAs poll each)

__device__ float gMem[TB * TD];    // recurrent state (in place; schedule-proven safe)
__device__ float gH[TB * TDD];     // hidden activations (in place)
__device__ __align__(256) unsigned gBarH[64];        // arrive ctr (root-polled only)
__device__ __align__(256) unsigned gBarM[64];
__device__ __align__(256) unsigned gBcH[NBC][64];    // root -> consumers
__device__ __align__(256) unsigned gBcM[NBC][64];

__global__ void init_scratch() {
    int t = blockIdx.x * blockDim.x + threadIdx.x;
    if (t < TB * TD) gMem[t] = 0.0f;
    if (t < 64) { gBarH[t] = 0u; gBarM[t] = 0u; }
    if (t < NBC * 64) { ((unsigned*)gBcH)[t] = 0u; ((unsigned*)gBcM)[t] = 0u; }
}

__device__ __forceinline__ void fma2(unsigned long long& acc,
                                     unsigned long long a,
                                     unsigned long long b) {
    asm volatile("fma.rn.f32x2 %0, %1, %2, %0;" : "+l"(acc) : "l"(a), "l"(b));
}
__device__ __forceinline__ float2 u2f(unsigned long long v) {
    float2 f;
    asm("mov.b64 {%0,%1}, %2;" : "=f"(f.x), "=f"(f.y) : "l"(v));
    return f;
}
__device__ __forceinline__ ulonglong2 ldg128_cg(const void* p) {
    ulonglong2 v;
    asm volatile("ld.global.cg.v2.u64 {%0,%1}, [%2];"
                 : "=l"(v.x), "=l"(v.y) : "l"(p));
    return v;
}
__device__ __forceinline__ ulonglong2 ldg128_nc(const void* p) {
    ulonglong2 v;
    asm volatile("ld.global.nc.v2.u64 {%0,%1}, [%2];"
                 : "=l"(v.x), "=l"(v.y) : "l"(p));
    return v;
}
__device__ __forceinline__ void stg_cg(float* p, float v) {
    asm volatile("st.global.cg.f32 [%0], %1;" :: "l"(p), "f"(v) : "memory");
}
// cumulative-release arrive (after __syncthreads: publishes the CTA's prior stores)
__device__ __forceinline__ void bar_arrive(unsigned* ctr) {
    unsigned one = 1u;
    asm volatile("red.release.gpu.global.add.u32 [%0], %1;"
                 :: "l"(ctr), "r"(one) : "memory");
}
// single-thread spin on one word
__device__ __forceinline__ void bar_spin(const unsigned* ctr, unsigned tgt) {
    unsigned v;
    do {
        asm volatile("ld.relaxed.gpu.global.u32 %0, [%1];"
                     : "=r"(v) : "l"(ctr) : "memory");
    } while (v < tgt);
}
__device__ __forceinline__ void st_rel(unsigned* p, unsigned v) {
    asm volatile("st.release.gpu.global.u32 [%0], %1;" :: "l"(p), "r"(v) : "memory");
}

// root (CTA 0) detects on the arrive counter, then fans out to NBC words;
// all other CTAs poll their dedicated broadcast word (8 pollers/word).
__device__ __forceinline__ void tree_wait(int cta, const unsigned* ctr,
                                          unsigned (*bc)[64],
                                          unsigned tgtCnt, unsigned gen) {
    if (cta == 0) {
        bar_spin(ctr, tgtCnt);
#pragma unroll
        for (int gword = 0; gword < NBC; ++gword) st_rel(&bc[gword][0], gen);
    } else {
        bar_spin(&bc[cta >> 3][0], gen);
    }
}

__global__ void __launch_bounds__(NTHR, 1)
sys2_kernel(const float* __restrict__ x,
            const float* __restrict__ W1,
            const float* __restrict__ b1,
            const float* __restrict__ W2,
            const float* __restrict__ b2,
            float* __restrict__ y)
{
    extern __shared__ float smem[];
    float* sW1   = smem;                     // CJ*TDD (32 KB)
    float* sW2   = sW1 + CJ * TDD;           // CI*TDD (16 KB)
    float* sPart = sW2 + CI * TDD;           // NWARP*64 = 512
    float* sB1   = sPart + NWARP * 64;       // CJ
    float* sB2   = sB1 + CJ;                 // CI

    const int cta  = blockIdx.x;
    const int tid  = threadIdx.x;
    const int w    = tid >> 5;
    const int lane = tid & 31;
    const int b    = lane >> 2;
    const int kq   = lane & 3;
    const int jbase = cta * CJ;
    const int ibase = cta * CI;

    {
        const float4* g1 = (const float4*)(W1 + (size_t)jbase * TDD);
        float4* s1 = (float4*)sW1;
        for (int idx = tid; idx < CJ * TDD / 4; idx += NTHR) s1[idx] = g1[idx];
        const float4* g2 = (const float4*)(W2 + (size_t)ibase * TDD);
        float4* s2 = (float4*)sW2;
        for (int idx = tid; idx < CI * TDD / 4; idx += NTHR) s2[idx] = g2[idx];
        if (tid < CJ) sB1[tid] = b1[jbase + tid];
        if (tid < CI) sB2[tid] = b2[ibase + tid];
    }
    __syncthreads();

    float memReg = 0.0f;   // tid<32 owns output (bb=tid>>2, ii=tid&3)

    ulonglong2 ex[4];
    {
        const float* xr = x + ((size_t)b * TT) * TD;
#pragma unroll
        for (int it = 0; it < 4; ++it)
            ex[it] = ldg128_nc(xr + (w << 6) + (it << 4) + (kq << 2));
    }

    for (int t = 0; t < TT; ++t) {
        // ===== Phase 1: h = gelu(W1 @ [x_t ; mem] + b1), j-slice =====
        unsigned long long ax[CJ], ay[CJ];
#pragma unroll
        for (int j = 0; j < CJ; ++j) { ax[j] = 0ull; ay[j] = 0ull; }

        // x-half part A (independent of mem) — overlaps the wait below
#pragma unroll
        for (int it = 0; it < 2; ++it) {
            const int k = (w << 6) + (it << 4) + (kq << 2);
#pragma unroll
            for (int j = 0; j < CJ; ++j) {
                const ulonglong2 wv = *(const ulonglong2*)(sW1 + j * TDD + k);
                fma2(ax[j], wv.x, ex[it].x);
                fma2(ay[j], wv.y, ex[it].y);
            }
        }

        if (t > 0 && tid == 0)
            tree_wait(cta, &gBarM[0], gBcM, (unsigned)t * NCTA, (unsigned)t);
        __syncthreads();                       // S1: mem(t-1) visible chip-wide

        // mem loads in flight under x-half part B
        const float* mrow = gMem + b * TD;
        ulonglong2 em[4];
#pragma unroll
        for (int it = 0; it < 4; ++it)
            em[it] = ldg128_cg(mrow + (w << 6) + (it << 4) + (kq << 2));

#pragma unroll
        for (int it = 2; it < 4; ++it) {
            const int k = (w << 6) + (it << 4) + (kq << 2);
#pragma unroll
            for (int j = 0; j < CJ; ++j) {
                const ulonglong2 wv = *(const ulonglong2*)(sW1 + j * TDD + k);
                fma2(ax[j], wv.x, ex[it].x);
                fma2(ay[j], wv.y, ex[it].y);
            }
        }
#pragma unroll
        for (int it = 0; it < 4; ++it) {
            const int k = (w << 6) + (it << 4) + (kq << 2);
#pragma unroll
            for (int j = 0; j < CJ; ++j) {
                const ulonglong2 wv = *(const ulonglong2*)(sW1 + j * TDD + TD + k);
                fma2(ax[j], wv.x, em[it].x);
                fma2(ay[j], wv.y, em[it].y);
            }
        }
#pragma unroll
        for (int j = 0; j < CJ; ++j) {
            const float2 fx = u2f(ax[j]);
            const float2 fy = u2f(ay[j]);
            float s = (fx.x + fx.y) + (fy.x + fy.y);
            s += __shfl_xor_sync(0xffffffffu, s, 1);
            s += __shfl_xor_sync(0xffffffffu, s, 2);
            if (kq == 0) sPart[(w << 6) + (b << 3) + j] = s;
        }
        __syncthreads();                       // S2

        // h-epilogue: threads 0..63, 1 output each
        if (tid < TB * CJ) {
            const int bb = tid >> 3, jj = tid & 7;
            float s = sB1[jj];
#pragma unroll
            for (int ww = 0; ww < NWARP; ++ww) s += sPart[(ww << 6) + tid];
            const float hval = 0.5f * s * (1.0f + erff(s * 0.70710678118654752f));
            stg_cg(&gH[bb * TDD + jbase + jj], hval);
        }
        __syncthreads();                       // S2b: h stores done CTA-wide
        if (tid == 0) bar_arrive(&gBarH[0]);

        // prefetch x(t+1) — overlaps the h-wait
        {
            const int tn = (t + 1 < TT) ? (t + 1) : t;
            const float* xr = x + ((size_t)b * TT + tn) * TD;
#pragma unroll
            for (int it = 0; it < 4; ++it)
                ex[it] = ldg128_nc(xr + (w << 6) + (it << 4) + (kq << 2));
        }

        if (tid == 0)
            tree_wait(cta, &gBarH[0], gBcH, (unsigned)(t + 1) * NCTA, (unsigned)(t + 1));
        __syncthreads();                       // S3: h(t) visible chip-wide

        // ===== Phase 2: p = W2 @ h + b2 ; gated mem update, i-slice =====
        const float* hrow = gH + b * TDD;
        ulonglong2 eh[8];
#pragma unroll
        for (int it = 0; it < 8; ++it)
            eh[it] = ldg128_cg(hrow + (w << 7) + (it << 4) + (kq << 2));

        unsigned long long px[CI], py[CI];
#pragma unroll
        for (int i = 0; i < CI; ++i) { px[i] = 0ull; py[i] = 0ull; }
#pragma unroll
        for (int it = 0; it < 8; ++it) {
            const int k = (w << 7) + (it << 4) + (kq << 2);
#pragma unroll
            for (int i = 0; i < CI; ++i) {
                const ulonglong2 wv = *(const ulonglong2*)(sW2 + i * TDD + k);
                fma2(px[i], wv.x, eh[it].x);
                fma2(py[i], wv.y, eh[it].y);
            }
        }
#pragma unroll
        for (int i = 0; i < CI; ++i) {
            const float2 fx = u2f(px[i]);
            const float2 fy = u2f(py[i]);
            float s = (fx.x + fx.y) + (fy.x + fy.y);
            s += __shfl_xor_sync(0xffffffffu, s, 1);
            s += __shfl_xor_sync(0xffffffffu, s, 2);
            if (kq == 0) sPart[(w << 5) + (b << 2) + i] = s;
        }
        __syncthreads();                       // S4

        // mem-epilogue: threads 0..31, 1 output each
        if (tid < TB * CI) {
            const int bb = tid >> 2, ii = tid & 3;
            float p = sB2[ii];
#pragma unroll
            for (int ww = 0; ww < NWARP; ++ww) p += sPart[(ww << 5) + tid];
            const float g = 1.0f / (1.0f + expf(-p));
            memReg = fmaf(p - memReg, g, memReg);
            stg_cg(&gMem[bb * TD + ibase + ii], memReg);
            y[((size_t)bb * TT + t) * TD + ibase + ii] = memReg;
        }
        __syncthreads();                       // S4b: mem stores done CTA-wide
        if (tid == 0) bar_arrive(&gBarM[0]);
    }
}

extern "C" void kernel_launch(void* const* d_in, const int* in_sizes, int n_in,
                              void* d_out, int out_size) {
    const float* x  = (const float*)d_in[0];
    const float* W1 = (const float*)d_in[1];
    const float* b1 = (const float*)d_in[2];
    const float* W2 = (const float*)d_in[3];
    const float* b2 = (const float*)d_in[4];
    float* y = (float*)d_out;

    const size_t SMEM_BYTES =
        (CJ * TDD + CI * TDD + NWARP * 64 + CJ + CI) * sizeof(float);
    cudaFuncSetAttribute(sys2_kernel,
                         cudaFuncAttributeMaxDynamicSharedMemorySize,
                         (int)SMEM_BYTES);

    init_scratch<<<(NBC * 64 + 255) / 256 > (TB * TD + 255) / 256 ?
                   (NBC * 64 + 255) / 256 : (TB * TD + 255) / 256, 256>>>();
    sys2_kernel<<<NCTA, NTHR, SMEM_BYTES>>>(x, W1, b1, W2, b2, y);
}

// round 14
// speedup vs baseline: 3.3538x; 3.3538x over previous
#include <cuda_runtime.h>
#include <math.h>

#define TB   8
#define TD   512
#define TDD  1024
#define TT   4096
#define NCTA 128
#define CJ   8        // h cols per CTA
#define CI   4        // p cols per CTA
#define NTHR 256
#define NWARP 8

__device__ float gMem[TB * TD];    // recurrent state (in place; schedule-proven safe)
__device__ float gH[TB * TDD];     // hidden activations (in place)
__device__ __align__(256) unsigned gBarH[64];   // arrivals after h(t) published
__device__ __align__(256) unsigned gBarM[64];   // arrivals after mem(t) published

__global__ void init_scratch() {
    int t = blockIdx.x * blockDim.x + threadIdx.x;
    if (t < TB * TD) gMem[t] = 0.0f;
    if (t < 64) { gBarH[t] = 0u; gBarM[t] = 0u; }
}

__device__ __forceinline__ void fma2(unsigned long long& acc,
                                     unsigned long long a,
                                     unsigned long long b) {
    asm volatile("fma.rn.f32x2 %0, %1, %2, %0;" : "+l"(acc) : "l"(a), "l"(b));
}
__device__ __forceinline__ float2 u2f(unsigned long long v) {
    float2 f;
    asm("mov.b64 {%0,%1}, %2;" : "=f"(f.x), "=f"(f.y) : "l"(v));
    return f;
}
__device__ __forceinline__ ulonglong2 ldg128_cg(const void* p) {
    ulonglong2 v;
    asm volatile("ld.global.cg.v2.u64 {%0,%1}, [%2];"
                 : "=l"(v.x), "=l"(v.y) : "l"(p));
    return v;
}
__device__ __forceinline__ ulonglong2 ldg128_nc(const void* p) {
    ulonglong2 v;
    asm volatile("ld.global.nc.v2.u64 {%0,%1}, [%2];"
                 : "=l"(v.x), "=l"(v.y) : "l"(p));
    return v;
}
__device__ __forceinline__ void stg_cg(float* p, float v) {
    asm volatile("st.global.cg.f32 [%0], %1;" :: "l"(p), "f"(v) : "memory");
}
// cumulative-release arrive (after CTA/warp-scope sync: publishes prior stores)
__device__ __forceinline__ void bar_arrive(unsigned* ctr) {
    unsigned one = 1u;
    asm volatile("red.release.gpu.global.add.u32 [%0], %1;"
                 :: "l"(ctr), "r"(one) : "memory");
}
// double-pumped spin on ONE word: two alternating in-flight loads halve the
// detect quantization (~300 -> ~150 cyc sampling period).
__device__ __forceinline__ void bar_spin2(const unsigned* ctr, unsigned tgt) {
    unsigned a, b;
    asm volatile("ld.relaxed.gpu.global.u32 %0, [%1];" : "=r"(a) : "l"(ctr) : "memory");
    for (;;) {
        asm volatile("ld.relaxed.gpu.global.u32 %0, [%1];" : "=r"(b) : "l"(ctr) : "memory");
        if (a >= tgt) break;
        asm volatile("ld.relaxed.gpu.global.u32 %0, [%1];" : "=r"(a) : "l"(ctr) : "memory");
        if (b >= tgt) break;
    }
}

__global__ void __launch_bounds__(NTHR, 1)
sys2_kernel(const float* __restrict__ x,
            const float* __restrict__ W1,
            const float* __restrict__ b1,
            const float* __restrict__ W2,
            const float* __restrict__ b2,
            float* __restrict__ y)
{
    extern __shared__ float smem[];
    float* sW1   = smem;                     // CJ*TDD (32 KB)
    float* sW2   = sW1 + CJ * TDD;           // CI*TDD (16 KB)
    float* sPart = sW2 + CI * TDD;           // NWARP*64 = 512
    float* sB1   = sPart + NWARP * 64;       // CJ
    float* sB2   = sB1 + CJ;                 // CI

    const int cta  = blockIdx.x;
    const int tid  = threadIdx.x;
    const int w    = tid >> 5;
    const int lane = tid & 31;
    const int b    = lane >> 2;
    const int kq   = lane & 3;
    const int jbase = cta * CJ;
    const int ibase = cta * CI;

    {
        const float4* g1 = (const float4*)(W1 + (size_t)jbase * TDD);
        float4* s1 = (float4*)sW1;
        for (int idx = tid; idx < CJ * TDD / 4; idx += NTHR) s1[idx] = g1[idx];
        const float4* g2 = (const float4*)(W2 + (size_t)ibase * TDD);
        float4* s2 = (float4*)sW2;
        for (int idx = tid; idx < CI * TDD / 4; idx += NTHR) s2[idx] = g2[idx];
        if (tid < CJ) sB1[tid] = b1[jbase + tid];
        if (tid < CI) sB2[tid] = b2[ibase + tid];
    }
    __syncthreads();

    float memReg = 0.0f;   // tid<32 owns output (bb=tid>>2, ii=tid&3)

    ulonglong2 ex[4];
    {
        const float* xr = x + ((size_t)b * TT) * TD;
#pragma unroll
        for (int it = 0; it < 4; ++it)
            ex[it] = ldg128_nc(xr + (w << 6) + (it << 4) + (kq << 2));
    }

    for (int t = 0; t < TT; ++t) {
        // ===== Phase 1: h = gelu(W1 @ [x_t ; mem] + b1), j-slice =====
        unsigned long long ax[CJ], ay[CJ];
#pragma unroll
        for (int j = 0; j < CJ; ++j) { ax[j] = 0ull; ay[j] = 0ull; }

        // x-half part A (independent of mem) — overlaps the spin below
#pragma unroll
        for (int it = 0; it < 2; ++it) {
            const int k = (w << 6) + (it << 4) + (kq << 2);
#pragma unroll
            for (int j = 0; j < CJ; ++j) {
                const ulonglong2 wv = *(const ulonglong2*)(sW1 + j * TDD + k);
                fma2(ax[j], wv.x, ex[it].x);
                fma2(ay[j], wv.y, ex[it].y);
            }
        }

        if (t > 0 && tid == 0) bar_spin2(&gBarM[0], (unsigned)t * NCTA);
        __syncthreads();                       // S1: mem(t-1) visible chip-wide

        // mem loads in flight under x-half part B
        const float* mrow = gMem + b * TD;
        ulonglong2 em[4];
#pragma unroll
        for (int it = 0; it < 4; ++it)
            em[it] = ldg128_cg(mrow + (w << 6) + (it << 4) + (kq << 2));

#pragma unroll
        for (int it = 2; it < 4; ++it) {
            const int k = (w << 6) + (it << 4) + (kq << 2);
#pragma unroll
            for (int j = 0; j < CJ; ++j) {
                const ulonglong2 wv = *(const ulonglong2*)(sW1 + j * TDD + k);
                fma2(ax[j], wv.x, ex[it].x);
                fma2(ay[j], wv.y, ex[it].y);
            }
        }
#pragma unroll
        for (int it = 0; it < 4; ++it) {
            const int k = (w << 6) + (it << 4) + (kq << 2);
#pragma unroll
            for (int j = 0; j < CJ; ++j) {
                const ulonglong2 wv = *(const ulonglong2*)(sW1 + j * TDD + TD + k);
                fma2(ax[j], wv.x, em[it].x);
                fma2(ay[j], wv.y, em[it].y);
            }
        }
#pragma unroll
        for (int j = 0; j < CJ; ++j) {
            const float2 fx = u2f(ax[j]);
            const float2 fy = u2f(ay[j]);
            float s = (fx.x + fx.y) + (fy.x + fy.y);
            s += __shfl_xor_sync(0xffffffffu, s, 1);
            s += __shfl_xor_sync(0xffffffffu, s, 2);
            if (kq == 0) sPart[(w << 6) + (b << 3) + j] = s;
        }
        __syncthreads();                       // S2

        // h-epilogue: threads 0..63, tree-sum, then warp-pair arrive (no S2b)
        if (tid < TB * CJ) {
            const int jj = tid & 7;
            const int bb = tid >> 3;
            const float s0 = sPart[0 * 64 + tid] + sPart[1 * 64 + tid];
            const float s1 = sPart[2 * 64 + tid] + sPart[3 * 64 + tid];
            const float s2 = sPart[4 * 64 + tid] + sPart[5 * 64 + tid];
            const float s3 = sPart[6 * 64 + tid] + sPart[7 * 64 + tid];
            const float s  = sB1[jj] + ((s0 + s1) + (s2 + s3));
            const float hval = 0.5f * s * (1.0f + erff(s * 0.70710678118654752f));
            stg_cg(&gH[bb * TDD + jbase + jj], hval);
        }
        if (tid < 64) {
            asm volatile("bar.sync 1, 64;" ::: "memory");   // warps 0-1 only
            if (tid == 0) bar_arrive(&gBarH[0]);
        }

        // prefetch x(t+1) — overlaps the h-wait (warps 2-7 get here early)
        {
            const int tn = (t + 1 < TT) ? (t + 1) : t;
            const float* xr = x + ((size_t)b * TT + tn) * TD;
#pragma unroll
            for (int it = 0; it < 4; ++it)
                ex[it] = ldg128_nc(xr + (w << 6) + (it << 4) + (kq << 2));
        }

        if (tid == 0) bar_spin2(&gBarH[0], (unsigned)(t + 1) * NCTA);
        __syncthreads();                       // S3: h(t) visible chip-wide

        // ===== Phase 2: p = W2 @ h + b2 ; gated mem update, i-slice =====
        const float* hrow = gH + b * TDD;
        ulonglong2 eh[8];
#pragma unroll
        for (int it = 0; it < 8; ++it)
            eh[it] = ldg128_cg(hrow + (w << 7) + (it << 4) + (kq << 2));

        unsigned long long px[CI], py[CI];
#pragma unroll
        for (int i = 0; i < CI; ++i) { px[i] = 0ull; py[i] = 0ull; }
#pragma unroll
        for (int it = 0; it < 8; ++it) {
            const int k = (w << 7) + (it << 4) + (kq << 2);
#pragma unroll
            for (int i = 0; i < CI; ++i) {
                const ulonglong2 wv = *(const ulonglong2*)(sW2 + i * TDD + k);
                fma2(px[i], wv.x, eh[it].x);
                fma2(py[i], wv.y, eh[it].y);
            }
        }
#pragma unroll
        for (int i = 0; i < CI; ++i) {
            const float2 fx = u2f(px[i]);
            const float2 fy = u2f(py[i]);
            float s = (fx.x + fx.y) + (fy.x + fy.y);
            s += __shfl_xor_sync(0xffffffffu, s, 1);
            s += __shfl_xor_sync(0xffffffffu, s, 2);
            if (kq == 0) sPart[(w << 5) + (b << 2) + i] = s;
        }
        __syncthreads();                       // S4

        // mem-epilogue: warp 0 only; syncwarp + lane0 arrive (no S4b);
        // y (DRAM) store moved AFTER the arrive, off the release path.
        if (tid < TB * CI) {
            const float s0 = sPart[0 * 32 + tid] + sPart[1 * 32 + tid];
            const float s1 = sPart[2 * 32 + tid] + sPart[3 * 32 + tid];
            const float s2 = sPart[4 * 32 + tid] + sPart[5 * 32 + tid];
            const float s3 = sPart[6 * 32 + tid] + sPart[7 * 32 + tid];
            const float p  = sB2[tid & 3] + ((s0 + s1) + (s2 + s3));
            const float g  = 1.0f / (1.0f + __expf(-p));
            memReg = fmaf(p - memReg, g, memReg);
            stg_cg(&gMem[(tid >> 2) * TD + ibase + (tid & 3)], memReg);
        }
        if (tid < 32) {
            __syncwarp();
            if (tid == 0) bar_arrive(&gBarM[0]);
            if (tid < TB * CI)
                y[((size_t)(tid >> 2) * TT + t) * TD + ibase + (tid & 3)] = memReg;
        }
    }
}

extern "C" void kernel_launch(void* const* d_in, const int* in_sizes, int n_in,
                              void* d_out, int out_size) {
    const float* x  = (const float*)d_in[0];
    const float* W1 = (const float*)d_in[1];
    const float* b1 = (const float*)d_in[2];
    const float* W2 = (const float*)d_in[3];
    const float* b2 = (const float*)d_in[4];
    float* y = (float*)d_out;

    const size_t SMEM_BYTES =
        (CJ * TDD + CI * TDD + NWARP * 64 + CJ + CI) * sizeof(float);
    cudaFuncSetAttribute(sys2_kernel,
                         cudaFuncAttributeMaxDynamicSharedMemorySize,
                         (int)SMEM_BYTES);

    init_scratch<<<(TB * TD + 255) / 256, 256>>>();
    sys2_kernel<<<NCTA, NTHR, SMEM_BYTES>>>(x, W1, b1, W2, b2, y);
}